// round 11
// baseline (speedup 1.0000x reference)
#include <cuda_runtime.h>

// RoiAlign FPN: B=2, N=1000, CROP=7x7, C=256, levels 256/128/64/32/16 (NHWC f32).
// 296 blocks x 320 threads; each block owns <=7 contiguous boxes.
// Phase 1: one thread per (box,pixel) computes params + per-pixel feat pointer
// into smem. Phase 2: flat pixel loop, 5 pixel-slots x 64 float4 channel groups,
// DEPTH-3 software pipeline (12 LDG.128 in flight/thread) -- each load gets two
// iterations to complete, halving exposed L2 latency vs depth-2.
// 320thr x 2 CTA/SM gives a 102-reg budget to hold the 3 stages.

#define C4 64  // 256 channels / 4

__global__ __launch_bounds__(320, 2) void roialign_kernel(
    const float* __restrict__ boxes,
    const float* __restrict__ f0, const float* __restrict__ f1,
    const float* __restrict__ f2, const float* __restrict__ f3,
    const float* __restrict__ f4,
    const int*   __restrict__ image_shape,
    float*       __restrict__ out,
    int N, int chunk, int rem)
{
    __shared__ float4 s_a[343];                // corner indices (int bitcast)
    __shared__ float4 s_b[343];                // lx, ly, okf, 0
    __shared__ const float4* s_fpp[343];       // per-pixel level base pointer

    const int bid = blockIdx.x;
    const int tid = threadIdx.x;

    // contiguous box range: first `rem` blocks get chunk+1 boxes
    const int start = bid * chunk + min(bid, rem);
    const int nb    = chunk + (bid < rem ? 1 : 0);   // <= 7
    const int total = nb * 49;

    // ---------------- Phase 1: params for all nb*49 pixels -------------------
    // 320 threads < 343 params: loop twice.
    for (int q = tid; q < total; q += 320) {
        const int bl   = q / 49;               // box slot 0..nb-1
        const int pixl = q % 49;
        const int boxg = start + bl;

        // NOTE: reference unpacks boxes[:,0] as "y1" though setup stacked
        // [x1,y1,x2,y2]; features are square so it's a consistent transpose.
        const float a0 = __ldg(boxes + (size_t)boxg * 4 + 0);
        const float a1 = __ldg(boxes + (size_t)boxg * 4 + 1);
        const float a2 = __ldg(boxes + (size_t)boxg * 4 + 2);
        const float a3 = __ldg(boxes + (size_t)boxg * 4 + 3);

        // lvl = clip(round(log2(sqrt(h*w) / (56/sqrt(area)))), 0, 4)
        const float h     = a3 - a1;
        const float w     = a2 - a0;
        const float area  = (float)(image_shape[0] * image_shape[1]);
        const float denom = 56.0f / sqrtf(area);
        int lvl = (int)rintf(log2f(sqrtf(h * w) / denom));  // round-half-even
        lvl = min(max(lvl, 0), 4);

        const int S = 256 >> lvl;
        const float* feat = (lvl == 0) ? f0 : (lvl == 1) ? f1
                          : (lvl == 2) ? f2 : (lvl == 3) ? f3 : f4;
        s_fpp[q] = (const float4*)feat;

        const float Hf = (float)(S - 1);
        const int gy = pixl / 7;
        const int gx = pixl % 7;

        // Exact reference op order: ys = y1*Hf + gy*((y2-y1)*Hf/6)
        const float ys = a0 * Hf + (float)gy * (((a2 - a0) * Hf) / 6.0f);
        const float xs = a1 * Hf + (float)gx * (((a3 - a1) * Hf) / 6.0f);

        const float y0f = floorf(ys);
        const float x0f = floorf(xs);
        const float ly  = ys - y0f;
        const float lx  = xs - x0f;

        const int y0 = (int)fminf(fmaxf(y0f,        0.0f), Hf);
        const int y1 = (int)fminf(fmaxf(y0f + 1.0f, 0.0f), Hf);
        const int x0 = (int)fminf(fmaxf(x0f,        0.0f), Hf);
        const int x1 = (int)fminf(fmaxf(x0f + 1.0f, 0.0f), Hf);

        const float okf = ((ys >= 0.0f) & (ys <= Hf) &
                           (xs >= 0.0f) & (xs <= Hf)) ? 1.0f : 0.0f;

        const int bS = (boxg / N) * S;
        const int r0 = (bS + y0) * S;
        const int r1 = (bS + y1) * S;
        // flat indices in float4 units (max ~8.4M, int32-safe)
        s_a[q] = make_float4(__int_as_float((r0 + x0) * C4),
                             __int_as_float((r0 + x1) * C4),
                             __int_as_float((r1 + x0) * C4),
                             __int_as_float((r1 + x1) * C4));
        s_b[q] = make_float4(lx, ly, okf, 0.0f);
    }
    __syncthreads();

    // ---------------- Phase 2: depth-3 pipelined gather + lerp ---------------
    const int psub = tid >> 6;        // pixel slot 0..4 (2 warps per slot)
    const int c    = tid & 63;        // float4 channel group 0..63
    float4* __restrict__ out4 = (float4*)out + (long)start * 49 * C4 + c;

    // Prologue: issue groups A (p) and B (p+5). total >= 294 so both valid.
    int pA = psub;
    {
    }
    const float4* fpA = s_fpp[pA];
    float4 qaA = s_a[pA];
    float4 qbA = s_b[pA];
    float4 a00 = __ldg(fpA + __float_as_int(qaA.x) + c);
    float4 a01 = __ldg(fpA + __float_as_int(qaA.y) + c);
    float4 a10 = __ldg(fpA + __float_as_int(qaA.z) + c);
    float4 a11 = __ldg(fpA + __float_as_int(qaA.w) + c);

    const int pB = psub + 5;
    const float4* fpB = s_fpp[pB];
    float4 qaB = s_a[pB];
    float4 qbB = s_b[pB];
    float4 b00 = __ldg(fpB + __float_as_int(qaB.x) + c);
    float4 b01 = __ldg(fpB + __float_as_int(qaB.y) + c);
    float4 b10 = __ldg(fpB + __float_as_int(qaB.z) + c);
    float4 b11 = __ldg(fpB + __float_as_int(qaB.w) + c);

    #pragma unroll 1
    for (int p = psub; p < total; p += 5) {
        // Stage C: issue loads for p+10 (clamped dummy near the tail)
        const int np  = p + 10;
        const int npc = (np < total) ? np : p;
        const float4* fpC = s_fpp[npc];
        const float4 qaC = s_a[npc];
        const float4 qbC = s_b[npc];
        float4 c00 = __ldg(fpC + __float_as_int(qaC.x) + c);
        float4 c01 = __ldg(fpC + __float_as_int(qaC.y) + c);
        float4 c10 = __ldg(fpC + __float_as_int(qaC.z) + c);
        float4 c11 = __ldg(fpC + __float_as_int(qaC.w) + c);

        // Compute + store group A (pixel p)
        const float lx = qbA.x, ly = qbA.y, okf = qbA.z;
        float4 val;
        {
            float t, btm;
            t = a00.x + lx * (a01.x - a00.x); btm = a10.x + lx * (a11.x - a10.x);
            val.x = (t + ly * (btm - t)) * okf;
            t = a00.y + lx * (a01.y - a00.y); btm = a10.y + lx * (a11.y - a10.y);
            val.y = (t + ly * (btm - t)) * okf;
            t = a00.z + lx * (a01.z - a00.z); btm = a10.z + lx * (a11.z - a10.z);
            val.z = (t + ly * (btm - t)) * okf;
            t = a00.w + lx * (a01.w - a00.w); btm = a10.w + lx * (a11.w - a10.w);
            val.w = (t + ly * (btm - t)) * okf;
        }
        out4[(long)p * C4] = val;

        // Rotate pipeline: A <- B <- C
        qbA = qbB;
        a00 = b00; a01 = b01; a10 = b10; a11 = b11;
        qbB = qbC;
        b00 = c00; b01 = c01; b10 = c10; b11 = c11;
    }
}

extern "C" void kernel_launch(void* const* d_in, const int* in_sizes, int n_in,
                              void* d_out, int out_size)
{
    const float* boxes = (const float*)d_in[0];
    const float* f0    = (const float*)d_in[1];
    const float* f1    = (const float*)d_in[2];
    const float* f2    = (const float*)d_in[3];
    const float* f3    = (const float*)d_in[4];
    const float* f4    = (const float*)d_in[5];
    const int*   ishp  = (const int*)d_in[6];

    const int BN = in_sizes[0] / 4;                    // B*N boxes
    const int B  = in_sizes[1] / (256 * 256 * 256);    // feat0 = B*256*256*256
    const int N  = BN / B;

    // 2 blocks per SM (296 on 148-SM GB300), each with <=7 contiguous boxes
    int grid = 296;
    if ((BN + 6) / 7 > grid) grid = (BN + 6) / 7;      // safety for larger BN
    const int chunk = BN / grid;
    const int rem   = BN % grid;

    roialign_kernel<<<grid, 320>>>(boxes, f0, f1, f2, f3, f4, ishp,
                                   (float*)d_out, N, chunk, rem);
}

// round 13
// speedup vs baseline: 1.2529x; 1.2529x over previous
#include <cuda_runtime.h>

// RoiAlign FPN: B=2, N=1000, CROP=7x7, C=256, levels 256/128/64/32/16 (NHWC f32).
// 296 blocks x 320 threads; each block owns <=7 contiguous boxes.
// Phase 1: params + per-pixel feat pointer into smem.
// Phase 2: flat pixel loop, 5 slots x 64 float4 channel groups, DEPTH-3
// software pipeline via manual 3-body unroll with static register sets
// (S0/S1/S2), zero rotation MOVs. Tail refills clamp to index 0 (always
// initialized) -- R12's crash was an uninitialized s_fpp read when both the
// prefetch index and the current pixel were past `total`.

#define C4 64  // 256 channels / 4

#define COMPUTE_AND_REFILL(S00, S01, S10, S11, QB, Q, NEXTQ)                  \
    do {                                                                      \
        const int q_ = (Q);                                                   \
        const float lx_ = QB.x, ly_ = QB.y, okf_ = QB.z;                      \
        float4 val_;                                                          \
        float t_, btm_;                                                       \
        t_ = S00.x + lx_ * (S01.x - S00.x);                                   \
        btm_ = S10.x + lx_ * (S11.x - S10.x);                                 \
        val_.x = (t_ + ly_ * (btm_ - t_)) * okf_;                             \
        t_ = S00.y + lx_ * (S01.y - S00.y);                                   \
        btm_ = S10.y + lx_ * (S11.y - S10.y);                                 \
        val_.y = (t_ + ly_ * (btm_ - t_)) * okf_;                             \
        t_ = S00.z + lx_ * (S01.z - S00.z);                                   \
        btm_ = S10.z + lx_ * (S11.z - S10.z);                                 \
        val_.z = (t_ + ly_ * (btm_ - t_)) * okf_;                             \
        t_ = S00.w + lx_ * (S01.w - S00.w);                                   \
        btm_ = S10.w + lx_ * (S11.w - S10.w);                                 \
        val_.w = (t_ + ly_ * (btm_ - t_)) * okf_;                             \
        if (q_ < total) out4[(long)q_ * C4] = val_;                           \
        /* tail-safe refill index: always a written s_fpp/s_a/s_b entry */    \
        const int nq_ = ((NEXTQ) < total) ? (NEXTQ)                           \
                        : ((q_ < total) ? q_ : 0);                            \
        const float4* nfp_ = s_fpp[nq_];                                      \
        const float4 nqa_ = s_a[nq_];                                         \
        QB = s_b[nq_];                                                        \
        S00 = __ldg(nfp_ + __float_as_int(nqa_.x) + c);                       \
        S01 = __ldg(nfp_ + __float_as_int(nqa_.y) + c);                       \
        S10 = __ldg(nfp_ + __float_as_int(nqa_.z) + c);                       \
        S11 = __ldg(nfp_ + __float_as_int(nqa_.w) + c);                       \
    } while (0)

__global__ __launch_bounds__(320, 2) void roialign_kernel(
    const float* __restrict__ boxes,
    const float* __restrict__ f0, const float* __restrict__ f1,
    const float* __restrict__ f2, const float* __restrict__ f3,
    const float* __restrict__ f4,
    const int*   __restrict__ image_shape,
    float*       __restrict__ out,
    int N, int chunk, int rem)
{
    __shared__ float4 s_a[343];                // corner indices (int bitcast)
    __shared__ float4 s_b[343];                // lx, ly, okf, 0
    __shared__ const float4* s_fpp[343];       // per-pixel level base pointer

    const int bid = blockIdx.x;
    const int tid = threadIdx.x;

    const int start = bid * chunk + min(bid, rem);
    const int nb    = chunk + (bid < rem ? 1 : 0);   // <= 7
    const int total = nb * 49;                       // >= 294 for BN=2000

    // ---------------- Phase 1: params for all nb*49 pixels -------------------
    for (int q = tid; q < total; q += 320) {
        const int bl   = q / 49;
        const int pixl = q % 49;
        const int boxg = start + bl;

        // NOTE: reference unpacks boxes[:,0] as "y1" though setup stacked
        // [x1,y1,x2,y2]; features are square so it's a consistent transpose.
        const float a0 = __ldg(boxes + (size_t)boxg * 4 + 0);
        const float a1 = __ldg(boxes + (size_t)boxg * 4 + 1);
        const float a2 = __ldg(boxes + (size_t)boxg * 4 + 2);
        const float a3 = __ldg(boxes + (size_t)boxg * 4 + 3);

        // lvl = clip(round(log2(sqrt(h*w) / (56/sqrt(area)))), 0, 4)
        const float h     = a3 - a1;
        const float w     = a2 - a0;
        const float area  = (float)(image_shape[0] * image_shape[1]);
        const float denom = 56.0f / sqrtf(area);
        int lvl = (int)rintf(log2f(sqrtf(h * w) / denom));  // round-half-even
        lvl = min(max(lvl, 0), 4);

        const int S = 256 >> lvl;
        const float* feat = (lvl == 0) ? f0 : (lvl == 1) ? f1
                          : (lvl == 2) ? f2 : (lvl == 3) ? f3 : f4;
        s_fpp[q] = (const float4*)feat;

        const float Hf = (float)(S - 1);
        const int gy = pixl / 7;
        const int gx = pixl % 7;

        // Exact reference op order: ys = y1*Hf + gy*((y2-y1)*Hf/6)
        const float ys = a0 * Hf + (float)gy * (((a2 - a0) * Hf) / 6.0f);
        const float xs = a1 * Hf + (float)gx * (((a3 - a1) * Hf) / 6.0f);

        const float y0f = floorf(ys);
        const float x0f = floorf(xs);
        const float ly  = ys - y0f;
        const float lx  = xs - x0f;

        const int y0 = (int)fminf(fmaxf(y0f,        0.0f), Hf);
        const int y1 = (int)fminf(fmaxf(y0f + 1.0f, 0.0f), Hf);
        const int x0 = (int)fminf(fmaxf(x0f,        0.0f), Hf);
        const int x1 = (int)fminf(fmaxf(x0f + 1.0f, 0.0f), Hf);

        const float okf = ((ys >= 0.0f) & (ys <= Hf) &
                           (xs >= 0.0f) & (xs <= Hf)) ? 1.0f : 0.0f;

        const int bS = (boxg / N) * S;
        const int r0 = (bS + y0) * S;
        const int r1 = (bS + y1) * S;
        s_a[q] = make_float4(__int_as_float((r0 + x0) * C4),
                             __int_as_float((r0 + x1) * C4),
                             __int_as_float((r1 + x0) * C4),
                             __int_as_float((r1 + x1) * C4));
        s_b[q] = make_float4(lx, ly, okf, 0.0f);
    }
    __syncthreads();

    // ---------------- Phase 2: depth-3, zero-rotation pipeline ---------------
    const int psub = tid >> 6;        // pixel slot 0..4
    const int c    = tid & 63;        // float4 channel group 0..63
    float4* __restrict__ out4 = (float4*)out + (long)start * 49 * C4 + c;

    // Prologue: fill S0 (p), S1 (p+5), S2 (p+10); total>=294 so all valid.
    const int p0 = psub;
    const float4* fpA = s_fpp[p0];
    float4 qbA = s_b[p0];
    float4 qaA = s_a[p0];
    float4 A00 = __ldg(fpA + __float_as_int(qaA.x) + c);
    float4 A01 = __ldg(fpA + __float_as_int(qaA.y) + c);
    float4 A10 = __ldg(fpA + __float_as_int(qaA.z) + c);
    float4 A11 = __ldg(fpA + __float_as_int(qaA.w) + c);

    const float4* fpB = s_fpp[p0 + 5];
    float4 qbB = s_b[p0 + 5];
    float4 qaB = s_a[p0 + 5];
    float4 B00 = __ldg(fpB + __float_as_int(qaB.x) + c);
    float4 B01 = __ldg(fpB + __float_as_int(qaB.y) + c);
    float4 B10 = __ldg(fpB + __float_as_int(qaB.z) + c);
    float4 B11 = __ldg(fpB + __float_as_int(qaB.w) + c);

    const float4* fpC = s_fpp[p0 + 10];
    float4 qbC = s_b[p0 + 10];
    float4 qaC = s_a[p0 + 10];
    float4 C00 = __ldg(fpC + __float_as_int(qaC.x) + c);
    float4 C01 = __ldg(fpC + __float_as_int(qaC.y) + c);
    float4 C10 = __ldg(fpC + __float_as_int(qaC.z) + c);
    float4 C11 = __ldg(fpC + __float_as_int(qaC.w) + c);

    #pragma unroll 1
    for (int p = p0; p < total; p += 15) {
        // body 0: pixel p, refill S0 with p+15 (used 3 bodies later)
        COMPUTE_AND_REFILL(A00, A01, A10, A11, qbA, p,      p + 15);
        // body 1: pixel p+5, refill S1 with p+20
        COMPUTE_AND_REFILL(B00, B01, B10, B11, qbB, p + 5,  p + 20);
        // body 2: pixel p+10, refill S2 with p+25
        COMPUTE_AND_REFILL(C00, C01, C10, C11, qbC, p + 10, p + 25);
    }
}

extern "C" void kernel_launch(void* const* d_in, const int* in_sizes, int n_in,
                              void* d_out, int out_size)
{
    const float* boxes = (const float*)d_in[0];
    const float* f0    = (const float*)d_in[1];
    const float* f1    = (const float*)d_in[2];
    const float* f2    = (const float*)d_in[3];
    const float* f3    = (const float*)d_in[4];
    const float* f4    = (const float*)d_in[5];
    const int*   ishp  = (const int*)d_in[6];

    const int BN = in_sizes[0] / 4;                    // B*N boxes
    const int B  = in_sizes[1] / (256 * 256 * 256);    // feat0 = B*256*256*256
    const int N  = BN / B;

    int grid = 296;
    if ((BN + 6) / 7 > grid) grid = (BN + 6) / 7;      // safety for larger BN
    const int chunk = BN / grid;
    const int rem   = BN % grid;

    roialign_kernel<<<grid, 320>>>(boxes, f0, f1, f2, f3, f4, ishp,
                                   (float*)d_out, N, chunk, rem);
}